// round 7
// baseline (speedup 1.0000x reference)
#include <cuda_runtime.h>
#include <math.h>
#include <stdint.h>

// ConvolutionalCapsule EM routing, R5: 2-CTA cluster splits the I axis.
// Each CTA: votes[72,16,16] fp32 in smem (90KB total -> 2 CTAs/SM, 32 warps).
// M-step partials exchanged with the cluster partner via DSMEM remote stores
// + mbarrier (release.cluster arrive / acquire.cluster wait), ping-pong buffer.
// Softmax over o is per-input-capsule -> stays CTA-local. Stats duplicated in
// both CTAs; rank 0 writes output.

#define EPS 1e-9f
#define LOG2E 1.4426950408889634f
#define NPOS 1152
#define IL 72              // input capsules per CTA
#define NPAIRL 1152        // IL*16

// smem float offsets
#define OFF_RR    18432    // [72][16] rr / patch alias
#define OFF_ACTS  19584    // [72] (+pad)
#define OFF_PC    19664    // [3][256] local combine (half h=1)
#define OFF_PC2   20432    // [2][3][256] peer partials, ping-pong
#define OFF_A     21968    // [256]
#define OFF_B     22224    // [256]
#define OFF_C     22480    // [16]
#define OFF_MBAR  22496    // 8B mbarrier (8-byte aligned)
#define SMEM_FLOATS 22504
#define SMEM_BYTES (SMEM_FLOATS * 4)

__device__ __forceinline__ uint32_t smem_u32(const void* p) {
    uint32_t a;
    asm("{ .reg .u64 tmp; cvta.to.shared.u64 tmp, %1; cvt.u32.u64 %0, tmp; }"
        : "=r"(a) : "l"(p));
    return a;
}

#define MBAR_WAIT_PARITY_CLUSTER(mb, par) do {                                   \
    uint32_t _m = (mb), _p = (par), _d;                                          \
    asm volatile("{\n\t.reg .pred p;\n\t"                                        \
        "mbarrier.try_wait.parity.acquire.cluster.shared::cta.b64 p, [%1], %2;\n\t" \
        "selp.b32 %0, 1, 0, p;\n\t}"                                             \
        : "=r"(_d) : "r"(_m), "r"(_p) : "memory");                               \
    if (!_d) {                                                                   \
        asm volatile("{\n\t.reg .pred P1;\n\t"                                   \
            "WL%=:\n\t"                                                          \
            "mbarrier.try_wait.parity.acquire.cluster.shared::cta.b64 P1, [%0], %1, 0x989680;\n\t" \
            "@P1 bra.uni WD%=;\n\t"                                              \
            "bra.uni WL%=;\n\t"                                                  \
            "WD%=:\n\t}"                                                         \
            :: "r"(_m), "r"(_p) : "memory");                                     \
    }                                                                            \
} while (0)

__global__ __launch_bounds__(512, 2) __cluster_dims__(2, 1, 1)
void caps_em_kernel(const float* __restrict__ pose_in,   // [8,14,14,256]
                    const float* __restrict__ act_in,    // [8,14,14,16]
                    const float* __restrict__ w,         // [144,16,4,4]
                    const float* __restrict__ beta_v,    // [16]
                    const float* __restrict__ beta_a,    // [16]
                    float* __restrict__ out)             // pose[1152,256] ++ act[1152,16]
{
    extern __shared__ float sm[];
    float* votes = sm;
    float* rr    = sm + OFF_RR;
    float* acts  = sm + OFF_ACTS;
    float* pc    = sm + OFF_PC;
    float* pc2   = sm + OFF_PC2;
    float* a_sm  = sm + OFF_A;
    float* b_sm  = sm + OFF_B;
    float* c_sm  = sm + OFF_C;

    const int n = blockIdx.x >> 1;
    const int x = n % 12;
    const int y = (n / 12) % 12;
    const int b = n / 144;
    const int t = threadIdx.x;
    const int rot = ((t & 3) + ((t >> 2) & 1)) & 3;   // conflict-free chunk rotation

    uint32_t r;
    asm("mov.u32 %0, %%cluster_ctarank;" : "=r"(r));
    const uint32_t peer = 1u - r;

    const uint32_t smb       = smem_u32(sm);
    const uint32_t mbar_loc  = smb + OFF_MBAR * 4;
    uint32_t peer_pc2, peer_mbar;
    asm("mapa.shared::cluster.u32 %0, %1, %2;" : "=r"(peer_pc2)
        : "r"(smb + OFF_PC2 * 4), "r"(peer));
    asm("mapa.shared::cluster.u32 %0, %1, %2;" : "=r"(peer_mbar)
        : "r"(mbar_loc), "r"(peer));

    // ---- mbarrier init, then cluster-wide visibility ----
    if (t == 0) {
        asm volatile("mbarrier.init.shared.b64 [%0], %1;"
                     :: "r"(mbar_loc), "r"(256u) : "memory");
    }
    __syncthreads();
    asm volatile("barrier.cluster.arrive.aligned;" ::: "memory");
    asm volatile("barrier.cluster.wait.aligned;" ::: "memory");

    // ---- load this CTA's 72 im2col rows (aliased into rr) + acts ----
    for (int idx = t; idx < NPAIRL; idx += 512) {
        const int gi = (int)r * IL + (idx >> 4);
        const int kp = gi >> 4;
        const int base = (b * 14 + (y + kp / 3)) * 14 + (x + kp % 3);
        rr[idx] = pose_in[base * 256 + (gi & 15) * 16 + (idx & 15)];
    }
    if (t < IL) {
        const int gi = (int)r * IL + t;
        const int kp = gi >> 4;
        const int base = (b * 14 + (y + kp / 3)) * 14 + (x + kp % 3);
        acts[t] = act_in[base * 16 + (gi & 15)];
    }
    __syncthreads();

    // ---- votes[i,o] = pose4[i] @ w[gi,o], rotated rows (conflict-free STS.128) ----
    for (int idx = t; idx < NPAIRL; idx += 512) {
        const int i = idx >> 4;
        const float4* pw = (const float4*)(w + (size_t)((int)r * NPAIRL + idx) * 16);
        const float4 w0 = pw[0], w1 = pw[1], w2 = pw[2], w3 = pw[3];
        const float* pr = rr + i * 16;
        float4* vout = (float4*)(votes + idx * 16);
        #pragma unroll
        for (int rq = 0; rq < 4; ++rq) {
            const int rw = (rq + rot) & 3;
            const float a0 = pr[rw * 4 + 0], a1 = pr[rw * 4 + 1];
            const float a2 = pr[rw * 4 + 2], a3 = pr[rw * 4 + 3];
            float4 res;
            res.x = a0 * w0.x + a1 * w1.x + a2 * w2.x + a3 * w3.x;
            res.y = a0 * w0.y + a1 * w1.y + a2 * w2.y + a3 * w3.y;
            res.z = a0 * w0.z + a1 * w1.z + a2 * w2.z + a3 * w3.z;
            res.w = a0 * w0.w + a1 * w1.w + a2 * w2.w + a3 * w3.w;
            vout[rw] = res;
        }
    }
    __syncthreads();

    const int tt = t & 255;
    const int h  = t >> 8;
    const int o  = tt >> 4;
    const int p  = tt & 15;
    float bv = 0.f, ba = 0.f;
    if (t < 256) { bv = beta_v[o]; ba = beta_a[o]; }
    const float4* vt4 = (const float4*)votes;

    for (int it = 0; it < 3; ++it) {
        // ---- M-step partials over this half's 36 local input capsules ----
        float S0 = 0.f, S1 = 0.f, S2 = 0.f;
        const int i0 = h * 36;
        if (it == 0) {
            #pragma unroll 4
            for (int i = i0; i < i0 + 36; ++i) {
                const float rp = acts[i] * 0.0625f;
                const float v  = votes[i * 256 + tt];
                const float t1 = rp * v;
                S0 += rp; S1 += t1; S2 += t1 * v;
            }
        } else {
            #pragma unroll 4
            for (int i = i0; i < i0 + 36; ++i) {
                const float rp = rr[i * 16 + o];          // already * acts (folded)
                const float v  = votes[i * 256 + tt];
                const float t1 = rp * v;
                S0 += rp; S1 += t1; S2 += t1 * v;
            }
        }
        if (h) { pc[tt] = S0; pc[256 + tt] = S1; pc[512 + tt] = S2; }
        __syncthreads();

        if (t < 256) {
            // local combine (this CTA's 72 i's)
            S0 += pc[t]; S1 += pc[256 + t]; S2 += pc[512 + t];

            // exchange with cluster partner
            const int buf = (it & 1) * 768;
            asm volatile("st.shared::cluster.f32 [%0], %1;"
                         :: "r"(peer_pc2 + (uint32_t)(buf + t) * 4), "f"(S0) : "memory");
            asm volatile("st.shared::cluster.f32 [%0], %1;"
                         :: "r"(peer_pc2 + (uint32_t)(buf + 256 + t) * 4), "f"(S1) : "memory");
            asm volatile("st.shared::cluster.f32 [%0], %1;"
                         :: "r"(peer_pc2 + (uint32_t)(buf + 512 + t) * 4), "f"(S2) : "memory");
            asm volatile("mbarrier.arrive.release.cluster.shared::cluster.b64 _, [%0];"
                         :: "r"(peer_mbar) : "memory");
            MBAR_WAIT_PARITY_CLUSTER(mbar_loc, (uint32_t)(it & 1));
            S0 += pc2[buf + t]; S1 += pc2[buf + 256 + t]; S2 += pc2[buf + 512 + t];

            const float mean = S1 / (S0 + EPS);
            float varsum = S2 - 2.f * mean * S1 + mean * mean * S0;
            varsum = fmaxf(varsum, 0.f);
            const float stdv = sqrtf(varsum / (S0 + EPS));
            const float lg   = logf(stdv + EPS);
            const float invd = 1.f / (2.f * stdv * stdv + EPS);
            const float av   = invd * LOG2E;
            const float bco  = mean * av;

            float L = lg, MB = mean * bco;
            #pragma unroll
            for (int d = 8; d; d >>= 1) {
                L  += __shfl_xor_sync(0xffffffffu, L,  d);
                MB += __shfl_xor_sync(0xffffffffu, MB, d);
            }

            const float costsum = (16.f * bv + L) * S0;
            const float itemp = 1.f + (float)it;
            const float oact = 1.f / (1.f + expf(-(itemp * (ba - costsum))));

            if (it == 2) {
                if (r == 0) {
                    out[n * 256 + t] = mean;
                    if (p == 0) out[NPOS * 256 + n * 16 + o] = oact;
                }
            } else {
                a_sm[t] = av;
                b_sm[t] = bco;
                if (p == 0) c_sm[o] = (logf(oact + EPS) - L) * LOG2E - MB;
            }
        }
        __syncthreads();
        if (it == 2) break;

        // ---- E-step (qq-outer, shuffle-free): zz2 = C[oo] - sum_p v*(v*a-2b) ----
        {
            const int oo = t & 15;
            float4 s0 = make_float4(0.f, 0.f, 0.f, 0.f);
            float4 s1 = make_float4(0.f, 0.f, 0.f, 0.f);
            #pragma unroll
            for (int qq = 0; qq < 4; ++qq) {
                const int q = (qq + rot) & 3;
                const float4 A = ((const float4*)a_sm)[(oo << 2) | q];
                float4 Bb = ((const float4*)b_sm)[(oo << 2) | q];
                Bb.x *= -2.f; Bb.y *= -2.f; Bb.z *= -2.f; Bb.w *= -2.f;

                float4 v = vt4[(t << 2) | q];
                s0.x = fmaf(v.x, fmaf(v.x, A.x, Bb.x), s0.x);
                s0.y = fmaf(v.y, fmaf(v.y, A.y, Bb.y), s0.y);
                s0.z = fmaf(v.z, fmaf(v.z, A.z, Bb.z), s0.z);
                s0.w = fmaf(v.w, fmaf(v.w, A.w, Bb.w), s0.w);

                v = vt4[((t + 512) << 2) | q];
                s1.x = fmaf(v.x, fmaf(v.x, A.x, Bb.x), s1.x);
                s1.y = fmaf(v.y, fmaf(v.y, A.y, Bb.y), s1.y);
                s1.z = fmaf(v.z, fmaf(v.z, A.z, Bb.z), s1.z);
                s1.w = fmaf(v.w, fmaf(v.w, A.w, Bb.w), s1.w);
            }
            const float C = c_sm[oo];
            rr[t]       = C - ((s0.x + s0.y) + (s0.z + s0.w));
            rr[t + 512] = C - ((s1.x + s1.y) + (s1.z + s1.w));

            if (t < 128) {                      // tail rows 64..71
                float4 s2 = make_float4(0.f, 0.f, 0.f, 0.f);
                #pragma unroll
                for (int qq = 0; qq < 4; ++qq) {
                    const int q = (qq + rot) & 3;
                    const float4 A = ((const float4*)a_sm)[(oo << 2) | q];
                    float4 Bb = ((const float4*)b_sm)[(oo << 2) | q];
                    Bb.x *= -2.f; Bb.y *= -2.f; Bb.z *= -2.f; Bb.w *= -2.f;
                    const float4 v = vt4[((t + 1024) << 2) | q];
                    s2.x = fmaf(v.x, fmaf(v.x, A.x, Bb.x), s2.x);
                    s2.y = fmaf(v.y, fmaf(v.y, A.y, Bb.y), s2.y);
                    s2.z = fmaf(v.z, fmaf(v.z, A.z, Bb.z), s2.z);
                    s2.w = fmaf(v.w, fmaf(v.w, A.w, Bb.w), s2.w);
                }
                rr[t + 1024] = C - ((s2.x + s2.y) + (s2.z + s2.w));
            }
        }
        __syncthreads();

        // ---- softmax over o (base 2) per local input capsule, scaled by acts ----
        if (t < IL) {
            float4 z[4];
            #pragma unroll
            for (int qq = 0; qq < 4; ++qq) {
                const int q = (qq + rot) & 3;
                z[qq] = ((const float4*)rr)[(t << 2) | q];
            }
            float mx = -3.4e38f;
            #pragma unroll
            for (int qq = 0; qq < 4; ++qq)
                mx = fmaxf(mx, fmaxf(fmaxf(z[qq].x, z[qq].y), fmaxf(z[qq].z, z[qq].w)));
            float ss = 0.f;
            #pragma unroll
            for (int qq = 0; qq < 4; ++qq) {
                z[qq].x = exp2f(z[qq].x - mx); ss += z[qq].x;
                z[qq].y = exp2f(z[qq].y - mx); ss += z[qq].y;
                z[qq].z = exp2f(z[qq].z - mx); ss += z[qq].z;
                z[qq].w = exp2f(z[qq].w - mx); ss += z[qq].w;
            }
            const float scale = acts[t] / ss;
            #pragma unroll
            for (int qq = 0; qq < 4; ++qq) {
                const int q = (qq + rot) & 3;
                float4 zz = z[qq];
                zz.x *= scale; zz.y *= scale; zz.z *= scale; zz.w *= scale;
                ((float4*)rr)[(t << 2) | q] = zz;
            }
        }
        __syncthreads();
    }

    // ---- cluster-safe exit ----
    asm volatile("barrier.cluster.arrive.aligned;" ::: "memory");
    asm volatile("barrier.cluster.wait.aligned;" ::: "memory");
}

extern "C" void kernel_launch(void* const* d_in, const int* in_sizes, int n_in,
                              void* d_out, int out_size) {
    const float* pose_in = (const float*)d_in[0];
    const float* act_in  = (const float*)d_in[1];
    const float* w       = (const float*)d_in[2];
    const float* beta_v  = (const float*)d_in[3];
    const float* beta_a  = (const float*)d_in[4];
    float* out = (float*)d_out;

    cudaFuncSetAttribute(caps_em_kernel,
                         cudaFuncAttributeMaxDynamicSharedMemorySize, SMEM_BYTES);
    caps_em_kernel<<<NPOS * 2, 512, SMEM_BYTES>>>(pose_in, act_in, w, beta_v, beta_a, out);
}

// round 9
// speedup vs baseline: 1.3148x; 1.3148x over previous
#include <cuda_runtime.h>
#include <math.h>
#include <stdint.h>

// ConvolutionalCapsule EM routing, R6: register-resident votes + packed f32x2.
// 512 threads/CTA, one CTA per output position (1152 CTAs).
// Thread t = h*64 + om*4 + pq: owns votes[i = h*18..h*18+17][om][pose row pq]
// as 18 x float4 in REGISTERS (built once, reused by all 3 M-steps + 2 E-steps).
// No votes array in shared memory at all (smem ~76KB).
// E-step partials go through a padded smem buffer; softmax combines them.

#define EPS 1e-9f
#define LOG2E 1.4426950408889634f
#define NPOS 1152
#define ICAP 144
#define NPAIR 2304

// smem float offsets
#define OFF_RR    0        // [144][16] rr (aliased: im2col pose patch)
#define OFF_ACTS  2304     // [144] (+pad)
#define OFF_PC    2464     // [512][12] M-step partials: S1[4],S2[4],S0,pad3
#define OFF_EP    8608     // [144][68] E-step partials (stride 17 float4, padded)
#define OFF_A     18400    // [256] invd*log2e        (indexed o*16+p)
#define OFF_B     18656    // [256] mean*invd*log2e
#define OFF_C     18912    // [16]
#define SMEM_FLOATS 18928
#define SMEM_BYTES (SMEM_FLOATS * 4)

typedef unsigned long long ull;

__device__ __forceinline__ ull pk2(float lo, float hi) {
    ull d;
    asm("mov.b64 %0, {%1, %2};" : "=l"(d)
        : "r"(__float_as_uint(lo)), "r"(__float_as_uint(hi)));
    return d;
}
__device__ __forceinline__ void upk2(ull v, float& lo, float& hi) {
    unsigned a, b;
    asm("mov.b64 {%0, %1}, %2;" : "=r"(a), "=r"(b) : "l"(v));
    lo = __uint_as_float(a); hi = __uint_as_float(b);
}
__device__ __forceinline__ ull fma2(ull a, ull b, ull c) {
    ull d; asm("fma.rn.f32x2 %0, %1, %2, %3;" : "=l"(d) : "l"(a), "l"(b), "l"(c));
    return d;
}
__device__ __forceinline__ ull mul2(ull a, ull b) {
    ull d; asm("mul.rn.f32x2 %0, %1, %2;" : "=l"(d) : "l"(a), "l"(b));
    return d;
}
__device__ __forceinline__ ull add2(ull a, ull b) {
    ull d; asm("add.rn.f32x2 %0, %1, %2;" : "=l"(d) : "l"(a), "l"(b));
    return d;
}

__global__ __launch_bounds__(512, 1)
void caps_em_kernel(const float* __restrict__ pose_in,   // [8,14,14,256]
                    const float* __restrict__ act_in,    // [8,14,14,16]
                    const float* __restrict__ w,         // [144,16,4,4]
                    const float* __restrict__ beta_v,    // [16]
                    const float* __restrict__ beta_a,    // [16]
                    float* __restrict__ out)             // pose[1152,256] ++ act[1152,16]
{
    extern __shared__ float sm[];
    float* rr   = sm + OFF_RR;
    float* acts = sm + OFF_ACTS;
    float* pc   = sm + OFF_PC;
    float* ep   = sm + OFF_EP;
    float* a_sm = sm + OFF_A;
    float* b_sm = sm + OFF_B;
    float* c_sm = sm + OFF_C;

    const int n = blockIdx.x;
    const int x = n % 12;
    const int y = (n / 12) % 12;
    const int b = n / 144;
    const int t = threadIdx.x;

    const int h  = t >> 6;          // 0..7  (I-octant: i = h*18 + j)
    const int om = (t >> 2) & 15;   // output capsule
    const int pq = t & 3;           // pose row (p = pq*4 + c)
    const int t63 = t & 63;         // om*4+pq
    // stats-phase mapping (t < 256)
    const int o = (t >> 4) & 15;
    const int p = t & 15;

    // ---- load im2col patch (into rr) + acts ----
    for (int idx = t; idx < NPAIR; idx += 512) {
        const int kp = idx >> 8, c = idx & 255;
        const int base = (b * 14 + (y + kp / 3)) * 14 + (x + kp % 3);
        rr[idx] = pose_in[base * 256 + c];
    }
    if (t < ICAP) {
        const int kp = t >> 4;
        const int base = (b * 14 + (y + kp / 3)) * 14 + (x + kp % 3);
        acts[t] = act_in[base * 16 + (t & 15)];
    }
    __syncthreads();

    // ---- build votes directly into registers ----
    // v[j] = pose row pq of capsule i=h*18+j (1x4) @ w[i][om] (4x4) -> 1x4
    ull va[18], vb[18];    // packed (c0,c1) and (c2,c3)
    {
        const int i0 = h * 18;
        #pragma unroll
        for (int j = 0; j < 18; ++j) {
            const int i = i0 + j;
            const float4 pr = ((const float4*)rr)[i * 4 + pq];  // pose[i][pq][0..3]
            const ulonglong2* wp =
                (const ulonglong2*)(w + ((size_t)i * 16 + om) * 16);
            const ulonglong2 w0 = wp[0], w1 = wp[1], w2 = wp[2], w3 = wp[3];
            const ull a0 = pk2(pr.x, pr.x), a1 = pk2(pr.y, pr.y);
            const ull a2 = pk2(pr.z, pr.z), a3 = pk2(pr.w, pr.w);
            ull s01 = mul2(a0, w0.x);
            ull s23 = mul2(a0, w0.y);
            s01 = fma2(a1, w1.x, s01);  s23 = fma2(a1, w1.y, s23);
            s01 = fma2(a2, w2.x, s01);  s23 = fma2(a2, w2.y, s23);
            s01 = fma2(a3, w3.x, s01);  s23 = fma2(a3, w3.y, s23);
            va[j] = s01; vb[j] = s23;
        }
    }

    float bv = 0.f, ba = 0.f;
    if (t < 256) { bv = beta_v[o]; ba = beta_a[o]; }

    const int i0 = h * 18;
    float* mypc = pc + t * 12;

    for (int it = 0; it < 3; ++it) {
        // ---- M-step partials from register votes ----
        float S0 = 0.f;
        ull S1a = 0, S1b = 0, S2a = 0, S2b = 0;   // 0 bits == (0.f,0.f)
        if (it == 0) {
            #pragma unroll
            for (int j = 0; j < 18; ++j) {
                const float rp = acts[i0 + j] * 0.0625f;
                const ull rp2 = pk2(rp, rp);
                const ull t01 = mul2(rp2, va[j]);
                const ull t23 = mul2(rp2, vb[j]);
                S0 += rp;
                S1a = add2(S1a, t01); S1b = add2(S1b, t23);
                S2a = fma2(t01, va[j], S2a); S2b = fma2(t23, vb[j], S2b);
            }
        } else {
            #pragma unroll
            for (int j = 0; j < 18; ++j) {
                const float rp = rr[(i0 + j) * 16 + om];   // already * acts (folded)
                const ull rp2 = pk2(rp, rp);
                const ull t01 = mul2(rp2, va[j]);
                const ull t23 = mul2(rp2, vb[j]);
                S0 += rp;
                S1a = add2(S1a, t01); S1b = add2(S1b, t23);
                S2a = fma2(t01, va[j], S2a); S2b = fma2(t23, vb[j], S2b);
            }
        }
        {
            ulonglong2 u;
            u.x = S1a; u.y = S1b; ((ulonglong2*)mypc)[0] = u;
            u.x = S2a; u.y = S2b; ((ulonglong2*)mypc)[1] = u;
            mypc[8] = S0;
        }
        __syncthreads();

        // ---- combine 8 partials + statistics (threads 0..255 = (o,p)) ----
        if (t < 256) {
            const int g  = o * 4 + (p >> 2);
            const int pe = p & 3;
            float s0 = 0.f, s1 = 0.f, s2 = 0.f;
            #pragma unroll
            for (int hh = 0; hh < 8; ++hh) {
                const float* q = pc + (size_t)(hh * 64 + g) * 12;
                s1 += q[pe]; s2 += q[4 + pe]; s0 += q[8];
            }
            const float mean = s1 / (s0 + EPS);
            float varsum = s2 - 2.f * mean * s1 + mean * mean * s0;
            varsum = fmaxf(varsum, 0.f);
            const float stdv = sqrtf(varsum / (s0 + EPS));
            const float lg   = logf(stdv + EPS);
            const float invd = 1.f / (2.f * stdv * stdv + EPS);
            const float av   = invd * LOG2E;
            const float bco  = mean * av;

            float L = lg, MB = mean * bco;
            #pragma unroll
            for (int d = 8; d; d >>= 1) {
                L  += __shfl_xor_sync(0xffffffffu, L,  d);
                MB += __shfl_xor_sync(0xffffffffu, MB, d);
            }

            const float costsum = (16.f * bv + L) * s0;
            const float itemp = 1.f + (float)it;
            const float oact = 1.f / (1.f + expf(-(itemp * (ba - costsum))));

            if (it == 2) {
                out[n * 256 + t] = mean;
                if (p == 0) out[NPOS * 256 + n * 16 + o] = oact;
            } else {
                a_sm[t] = av;
                b_sm[t] = bco;
                if (p == 0) c_sm[o] = (logf(oact + EPS) - L) * LOG2E - MB;
            }
        }
        if (it == 2) break;
        __syncthreads();

        // ---- E-step partials from register votes ----
        // P[i,om,pq] = sum_{c in quad} v*(v*a - 2b)   (log2 space)
        {
            const ulonglong2 Av = ((const ulonglong2*)a_sm)[t63];
            ulonglong2 Bv = ((const ulonglong2*)b_sm)[t63];
            const ull n2 = pk2(-2.f, -2.f);
            const ull B01 = mul2(Bv.x, n2);
            const ull B23 = mul2(Bv.y, n2);
            #pragma unroll
            for (int j = 0; j < 18; ++j) {
                const ull u01 = fma2(va[j], Av.x, B01);
                const ull u23 = fma2(vb[j], Av.y, B23);
                ull s = mul2(va[j], u01);
                s = fma2(vb[j], u23, s);
                float lo, hi; upk2(s, lo, hi);
                ep[(i0 + j) * 68 + t63] = lo + hi;
            }
        }
        __syncthreads();

        // ---- fused pass2 + softmax per input capsule (threads 0..143) ----
        if (t < ICAP) {
            const float4* eprow = ((const float4*)ep) + t * 17;
            float zz[16];
            float mx = -3.4e38f;
            #pragma unroll
            for (int oo = 0; oo < 16; ++oo) {
                const float4 P = eprow[oo];
                const float z = c_sm[oo] - ((P.x + P.y) + (P.z + P.w));
                zz[oo] = z;
                mx = fmaxf(mx, z);
            }
            float ss = 0.f;
            #pragma unroll
            for (int oo = 0; oo < 16; ++oo) {
                zz[oo] = exp2f(zz[oo] - mx);
                ss += zz[oo];
            }
            const float scale = acts[t] / ss;    // fold acts into rr
            float4* rrow = ((float4*)rr) + t * 4;
            #pragma unroll
            for (int qq = 0; qq < 4; ++qq) {
                float4 zq;
                zq.x = zz[qq * 4 + 0] * scale;
                zq.y = zz[qq * 4 + 1] * scale;
                zq.z = zz[qq * 4 + 2] * scale;
                zq.w = zz[qq * 4 + 3] * scale;
                rrow[qq] = zq;
            }
        }
        __syncthreads();
    }
}

extern "C" void kernel_launch(void* const* d_in, const int* in_sizes, int n_in,
                              void* d_out, int out_size) {
    const float* pose_in = (const float*)d_in[0];
    const float* act_in  = (const float*)d_in[1];
    const float* w       = (const float*)d_in[2];
    const float* beta_v  = (const float*)d_in[3];
    const float* beta_a  = (const float*)d_in[4];
    float* out = (float*)d_out;

    cudaFuncSetAttribute(caps_em_kernel,
                         cudaFuncAttributeMaxDynamicSharedMemorySize, SMEM_BYTES);
    caps_em_kernel<<<NPOS, 512, SMEM_BYTES>>>(pose_in, act_in, w, beta_v, beta_a, out);
}

// round 10
// speedup vs baseline: 1.3380x; 1.0177x over previous
#include <cuda_runtime.h>
#include <math.h>
#include <stdint.h>

// ConvolutionalCapsule EM routing, R7: register votes + distributed inline
// stats + paired-lane softmax + direct-gmem vote build.
// 512 threads/CTA, one CTA per output position (1152 CTAs).
// Thread t = h*64 + om*4 + pq owns votes[i=h*18..+17][om][pose row pq] in regs.

#define EPS 1e-9f
#define LOG2E 1.4426950408889634f
#define NPOS 1152
#define ICAP 144

// smem float offsets
#define OFF_RR   0        // [144][16] rr
#define OFF_ACTS 2304     // [144] (+pad)
#define OFF_PC1  2464     // S1: [8][64] float4  (2048 floats)
#define OFF_PC2  4512     // S2: [8][64] float4  (2048 floats)
#define OFF_PC0  6560     // S0: [8][64]         (512 floats)
#define OFF_EP   7072     // [144][68] E-step cells (stride 17 float4)
#define SMEM_FLOATS 16864
#define SMEM_BYTES (SMEM_FLOATS * 4)

typedef unsigned long long ull;

__device__ __forceinline__ ull pk2(float lo, float hi) {
    ull d;
    asm("mov.b64 %0, {%1, %2};" : "=l"(d)
        : "r"(__float_as_uint(lo)), "r"(__float_as_uint(hi)));
    return d;
}
__device__ __forceinline__ void upk2(ull v, float& lo, float& hi) {
    unsigned a, b;
    asm("mov.b64 {%0, %1}, %2;" : "=r"(a), "=r"(b) : "l"(v));
    lo = __uint_as_float(a); hi = __uint_as_float(b);
}
__device__ __forceinline__ ull fma2(ull a, ull b, ull c) {
    ull d; asm("fma.rn.f32x2 %0, %1, %2, %3;" : "=l"(d) : "l"(a), "l"(b), "l"(c));
    return d;
}
__device__ __forceinline__ ull mul2(ull a, ull b) {
    ull d; asm("mul.rn.f32x2 %0, %1, %2;" : "=l"(d) : "l"(a), "l"(b));
    return d;
}
__device__ __forceinline__ ull add2(ull a, ull b) {
    ull d; asm("add.rn.f32x2 %0, %1, %2;" : "=l"(d) : "l"(a), "l"(b));
    return d;
}

__global__ __launch_bounds__(512, 1)
void caps_em_kernel(const float* __restrict__ pose_in,   // [8,14,14,256]
                    const float* __restrict__ act_in,    // [8,14,14,16]
                    const float* __restrict__ w,         // [144,16,4,4]
                    const float* __restrict__ beta_v,    // [16]
                    const float* __restrict__ beta_a,    // [16]
                    float* __restrict__ out)             // pose[1152,256] ++ act[1152,16]
{
    extern __shared__ float sm[];
    float* rr   = sm + OFF_RR;
    float* acts = sm + OFF_ACTS;
    float* pc1  = sm + OFF_PC1;
    float* pc2  = sm + OFF_PC2;
    float* pc0  = sm + OFF_PC0;
    float* ep   = sm + OFF_EP;

    const int n = blockIdx.x;
    const int x = n % 12;
    const int y = (n / 12) % 12;
    const int b = n / 144;
    const int t = threadIdx.x;

    const int h   = t >> 6;         // I-octant: i = h*18 + j
    const int t63 = t & 63;         // om*4 + pq
    const int om  = (t >> 2) & 15;  // output capsule
    const int pq  = t & 3;          // pose row quad (p = pq*4 + c)
    const int i0  = h * 18;

    // ---- stage acts (async w.r.t. vote build) ----
    if (t < ICAP) {
        const int kp = t >> 4;
        const int base = (b * 14 + (y + kp / 3)) * 14 + (x + kp % 3);
        acts[t] = act_in[base * 16 + (t & 15)];
    }

    // ---- build votes directly from gmem into registers ----
    // v[j] = pose row pq of capsule i (1x4) @ w[i][om] (4x4)
    ull va[18], vb[18];
    #pragma unroll
    for (int j = 0; j < 18; ++j) {
        const int i  = i0 + j;
        const int kp = i >> 4, ic = i & 15;
        const int base = (b * 14 + (y + kp / 3)) * 14 + (x + kp % 3);
        const float4 pr = *(const float4*)(pose_in + (size_t)base * 256 + ic * 16 + pq * 4);
        const ulonglong2* wp = (const ulonglong2*)(w + ((size_t)i * 16 + om) * 16);
        const ulonglong2 w0 = wp[0], w1 = wp[1], w2 = wp[2], w3 = wp[3];
        const ull a0 = pk2(pr.x, pr.x), a1 = pk2(pr.y, pr.y);
        const ull a2 = pk2(pr.z, pr.z), a3 = pk2(pr.w, pr.w);
        ull s01 = mul2(a0, w0.x);
        ull s23 = mul2(a0, w0.y);
        s01 = fma2(a1, w1.x, s01);  s23 = fma2(a1, w1.y, s23);
        s01 = fma2(a2, w2.x, s01);  s23 = fma2(a2, w2.y, s23);
        s01 = fma2(a3, w3.x, s01);  s23 = fma2(a3, w3.y, s23);
        va[j] = s01; vb[j] = s23;
    }

    const float bv = beta_v[om];
    const float ba = beta_a[om];
    __syncthreads();   // acts ready

    for (int it = 0; it < 3; ++it) {
        // ---- M-step partials from register votes ----
        float S0 = 0.f;
        ull S1a = 0, S1b = 0, S2a = 0, S2b = 0;
        if (it == 0) {
            #pragma unroll
            for (int j = 0; j < 18; ++j) {
                const float rp = acts[i0 + j] * 0.0625f;
                const ull rp2 = pk2(rp, rp);
                const ull t01 = mul2(rp2, va[j]);
                const ull t23 = mul2(rp2, vb[j]);
                S0 += rp;
                S1a = add2(S1a, t01); S1b = add2(S1b, t23);
                S2a = fma2(t01, va[j], S2a); S2b = fma2(t23, vb[j], S2b);
            }
        } else {
            #pragma unroll
            for (int j = 0; j < 18; ++j) {
                const float rp = rr[(i0 + j) * 16 + om];   // already * acts (folded)
                const ull rp2 = pk2(rp, rp);
                const ull t01 = mul2(rp2, va[j]);
                const ull t23 = mul2(rp2, vb[j]);
                S0 += rp;
                S1a = add2(S1a, t01); S1b = add2(S1b, t23);
                S2a = fma2(t01, va[j], S2a); S2b = fma2(t23, vb[j], S2b);
            }
        }
        {
            ulonglong2 u;
            u.x = S1a; u.y = S1b; ((ulonglong2*)pc1)[h * 64 + t63] = u;
            u.x = S2a; u.y = S2b; ((ulonglong2*)pc2)[h * 64 + t63] = u;
            pc0[h * 64 + t63] = S0;
        }
        __syncthreads();

        const bool last = (it == 2);
        if (last && t >= 64) return;   // only 64 threads needed for final stats

        // ---- distributed inline stats (all threads; redundant across h) ----
        float4 s1 = make_float4(0.f, 0.f, 0.f, 0.f);
        float4 s2 = make_float4(0.f, 0.f, 0.f, 0.f);
        float   s0 = 0.f;
        #pragma unroll
        for (int hh = 0; hh < 8; ++hh) {
            const float4 u1 = ((const float4*)pc1)[hh * 64 + t63];
            const float4 u2 = ((const float4*)pc2)[hh * 64 + t63];
            s1.x += u1.x; s1.y += u1.y; s1.z += u1.z; s1.w += u1.w;
            s2.x += u2.x; s2.y += u2.y; s2.z += u2.z; s2.w += u2.w;
            s0 += pc0[hh * 64 + t63];
        }
        const float inv_rs = __fdividef(1.f, s0 + EPS);
        float mean[4], av[4], bco[4];
        float L4 = 0.f, MB4 = 0.f;
        {
            const float s1v[4] = {s1.x, s1.y, s1.z, s1.w};
            const float s2v[4] = {s2.x, s2.y, s2.z, s2.w};
            #pragma unroll
            for (int c = 0; c < 4; ++c) {
                const float m = s1v[c] * inv_rs;
                float varsum = s2v[c] - 2.f * m * s1v[c] + m * m * s0;
                varsum = fmaxf(varsum, 0.f);
                const float stdv = sqrtf(varsum * inv_rs);
                const float lg   = __logf(stdv + EPS);
                const float invd = __fdividef(1.f, 2.f * stdv * stdv + EPS);
                mean[c] = m;
                av[c]   = invd * LOG2E;
                bco[c]  = m * av[c];
                L4  += lg;
                MB4 += m * bco[c];
            }
        }
        // sum over all 16 p: combine across the 4 pq lanes (adjacent lanes)
        float L = L4, MBs = MB4;
        L   += __shfl_xor_sync(0xffffffffu, L, 1);
        L   += __shfl_xor_sync(0xffffffffu, L, 2);
        MBs += __shfl_xor_sync(0xffffffffu, MBs, 1);
        MBs += __shfl_xor_sync(0xffffffffu, MBs, 2);

        const float costsum = (16.f * bv + L) * s0;
        const float itemp = 1.f + (float)it;
        const float oact = __fdividef(1.f, 1.f + __expf(-(itemp * (ba - costsum))));

        if (last) {
            // h==0 threads (t<64) write outputs
            float4 mv = make_float4(mean[0], mean[1], mean[2], mean[3]);
            ((float4*)out)[n * 64 + t63] = mv;
            if (pq == 0) out[NPOS * 256 + n * 16 + om] = oact;
            return;
        }

        // C folded per-quadrant into ep cells (C/4 each, sums back to C)
        const float C4 = ((__logf(oact + EPS) - L) * LOG2E - MBs) * 0.25f;
        const ull A01 = pk2(av[0], av[1]),  A23 = pk2(av[2], av[3]);
        const ull B01 = pk2(-2.f * bco[0], -2.f * bco[1]);
        const ull B23 = pk2(-2.f * bco[2], -2.f * bco[3]);

        // ---- E-step cells from register votes ----
        #pragma unroll
        for (int j = 0; j < 18; ++j) {
            const ull u01 = fma2(va[j], A01, B01);
            const ull u23 = fma2(vb[j], A23, B23);
            ull s = mul2(va[j], u01);
            s = fma2(vb[j], u23, s);
            float lo, hi; upk2(s, lo, hi);
            ep[(i0 + j) * 68 + t63] = C4 - (lo + hi);
        }
        __syncthreads();

        // ---- paired-lane softmax: lanes (2i, 2i+1) split the 16 o's ----
        if (t < 2 * ICAP) {
            const int i = t >> 1, half = t & 1;
            const float4* eprow = (const float4*)(ep + i * 68);
            float z[8];
            float mx = -3.4e38f;
            #pragma unroll
            for (int k = 0; k < 8; ++k) {
                const int kk = (k + 4 * half) & 7;        // bank stagger between halves
                const float4 P = eprow[half * 8 + kk];
                const float zz = (P.x + P.y) + (P.z + P.w);
                z[kk] = zz;
                mx = fmaxf(mx, zz);
            }
            mx = fmaxf(mx, __shfl_xor_sync(0xffffffffu, mx, 1));
            float ss = 0.f;
            #pragma unroll
            for (int k = 0; k < 8; ++k) {
                z[k] = exp2f(z[k] - mx);
                ss += z[k];
            }
            ss += __shfl_xor_sync(0xffffffffu, ss, 1);
            const float scale = acts[i] * __fdividef(1.f, ss);   // fold acts into rr
            float4 r0, r1;
            r0.x = z[0] * scale; r0.y = z[1] * scale; r0.z = z[2] * scale; r0.w = z[3] * scale;
            r1.x = z[4] * scale; r1.y = z[5] * scale; r1.z = z[6] * scale; r1.w = z[7] * scale;
            float4* dst = (float4*)(rr + i * 16 + half * 8);
            dst[0] = r0; dst[1] = r1;
        }
        __syncthreads();
    }
}

extern "C" void kernel_launch(void* const* d_in, const int* in_sizes, int n_in,
                              void* d_out, int out_size) {
    const float* pose_in = (const float*)d_in[0];
    const float* act_in  = (const float*)d_in[1];
    const float* w       = (const float*)d_in[2];
    const float* beta_v  = (const float*)d_in[3];
    const float* beta_a  = (const float*)d_in[4];
    float* out = (float*)d_out;

    cudaFuncSetAttribute(caps_em_kernel,
                         cudaFuncAttributeMaxDynamicSharedMemorySize, SMEM_BYTES);
    caps_em_kernel<<<NPOS, 512, SMEM_BYTES>>>(pose_in, act_in, w, beta_v, beta_a, out);
}